// round 10
// baseline (speedup 1.0000x reference)
#include <cuda_runtime.h>
#include <cuda_bf16.h>
#include <mma.h>
#include <math.h>
using namespace nvcuda;

#define NB 8
#define NC 128
#define NN 20000
#define TN 128
#define NT 157
#define LDT 136
#define LDTB 272
#define EPSV 1e-5f
#define INVTEMP 0.08838834764831845f  // 1/sqrt(128)

typedef unsigned int u32;
typedef __nv_bfloat16 bf16;

// scratch (__device__ statics)
__device__ bf16 g_vh[(size_t)NB * NT * TN * NC];   // v hi, [b][tile][d][n], 41 MB
__device__ bf16 g_vl[(size_t)NB * NT * TN * NC];   // v lo
__device__ float g_attn[(size_t)NB * NC * NC];
__device__ bf16 g_ah[(size_t)NB * NC * NC];        // softmaxed attn hi [b][c][d]
__device__ bf16 g_al[(size_t)NB * NC * NC];
__device__ float g_par[11 * NC];
__device__ bf16 g_Wb[3][2][NC * NC];               // W [o][c] bf16 hi/lo

// proj smem byte offsets
#define PB_HI 0            // pc^T [n][c] (later kg [d][n]) 128x136 bf16
#define PB_LO 34816
#define PQ_HI 69632        // qs [c][n]
#define PQ_LO 104448
#define PX    139264       // 512 floats
#define PSTG  141312       // 16 warps x 320 floats
#define SMEM_A_BYTES 161792

typedef wmma::fragment<wmma::matrix_a, 16, 16, 16, bf16, wmma::row_major> FragA;
typedef wmma::fragment<wmma::matrix_b, 16, 16, 16, bf16, wmma::col_major> FragBc;
typedef wmma::fragment<wmma::matrix_b, 16, 16, 16, bf16, wmma::row_major> FragBr;
typedef wmma::fragment<wmma::accumulator, 16, 16, 16, float> FragC;

__device__ __forceinline__ u32 split_pair(float a, float b, u32& lo_pair) {
    bf16 ha = __float2bfloat16(a);
    bf16 hb = __float2bfloat16(b);
    bf16 la = __float2bfloat16(a - __bfloat162float(ha));
    bf16 lb = __float2bfloat16(b - __bfloat162float(hb));
    lo_pair = (u32)__bfloat16_as_ushort(la) | ((u32)__bfloat16_as_ushort(lb) << 16);
    return (u32)__bfloat16_as_ushort(ha) | ((u32)__bfloat16_as_ushort(hb) << 16);
}

// 32x32 warp tile of 128x128x128 GEMM, bf16 split (hh+hl+lh). A row-major, B col-major.
__device__ __forceinline__ void gemm3(const bf16* AH, const bf16* AL, int lda,
                                      const bf16* BH, const bf16* BL, int ldb,
                                      int wm, int wn, FragC acc[2][2])
{
#pragma unroll
    for (int i = 0; i < 2; i++)
#pragma unroll
        for (int j = 0; j < 2; j++) wmma::fill_fragment(acc[i][j], 0.f);
#pragma unroll
    for (int k = 0; k < 8; k++) {
        FragA ah[2], al[2];
        FragBc bh[2], bl[2];
#pragma unroll
        for (int i = 0; i < 2; i++) {
            wmma::load_matrix_sync(ah[i], AH + (size_t)(wm + 16 * i) * lda + 16 * k, lda);
            wmma::load_matrix_sync(al[i], AL + (size_t)(wm + 16 * i) * lda + 16 * k, lda);
        }
#pragma unroll
        for (int j = 0; j < 2; j++) {
            wmma::load_matrix_sync(bh[j], BH + (size_t)(wn + 16 * j) * ldb + 16 * k, ldb);
            wmma::load_matrix_sync(bl[j], BL + (size_t)(wn + 16 * j) * ldb + 16 * k, ldb);
        }
#pragma unroll
        for (int i = 0; i < 2; i++)
#pragma unroll
            for (int j = 0; j < 2; j++) {
                wmma::mma_sync(acc[i][j], ah[i], bh[j], acc[i][j]);
                wmma::mma_sync(acc[i][j], ah[i], bl[j], acc[i][j]);
                wmma::mma_sync(acc[i][j], al[i], bh[j], acc[i][j]);
            }
    }
}

__device__ __forceinline__ void frag_vals(float* ws, const FragC& f, int lane, float* v)
{
    wmma::store_matrix_sync(ws, f, 20, wmma::mem_row_major);
    __syncwarp();
    const float* p = ws + (lane >> 1) * 20 + (lane & 1) * 8;
    float4 a = *(const float4*)p;
    float4 b = *(const float4*)(p + 4);
    v[0] = a.x; v[1] = a.y; v[2] = a.z; v[3] = a.w;
    v[4] = b.x; v[5] = b.y; v[6] = b.z; v[7] = b.w;
    __syncwarp();
}

__global__ void prep_kernel(const float* __restrict__ Wq, const float* __restrict__ Wk,
                            const float* __restrict__ Wv,
                            const float* __restrict__ gq, const float* __restrict__ bq,
                            const float* __restrict__ mq, const float* __restrict__ vq,
                            const float* __restrict__ gk, const float* __restrict__ bk,
                            const float* __restrict__ mk, const float* __restrict__ vk,
                            const float* __restrict__ gv, const float* __restrict__ bv,
                            const float* __restrict__ mv, const float* __restrict__ vv,
                            const float* __restrict__ Wg1, const float* __restrict__ bg1,
                            const float* __restrict__ Wg2, const float* __restrict__ bg2)
{
    int t = threadIdx.x;
    if (t < NC) {
        int o = t;
        float s;
        s = gq[o] * rsqrtf(vq[o] + EPSV); g_par[o]       = s; g_par[128 + o] = bq[o] - mq[o] * s;
        s = gk[o] * rsqrtf(vk[o] + EPSV); g_par[256 + o] = s; g_par[384 + o] = bk[o] - mk[o] * s;
        s = gv[o] * rsqrtf(vv[o] + EPSV); g_par[512 + o] = s; g_par[640 + o] = bv[o] - mv[o] * s;
        g_par[768 + o]  = Wg1[o * 2];
        g_par[896 + o]  = Wg1[o * 2 + 1];
        g_par[1024 + o] = Wg2[o * 2];
        g_par[1152 + o] = Wg2[o * 2 + 1];
        g_par[1280 + o] = bg1[o] + bg2[o];
    }
    for (int idx = t; idx < NB * NC * NC; idx += blockDim.x)
        g_attn[idx] = 0.f;
    for (int idx = t; idx < 3 * NC * NC; idx += blockDim.x) {
        int m = idx >> 14, e = idx & 16383;
        const float* Wp = (m == 0) ? Wq : (m == 1) ? Wk : Wv;
        float w = Wp[e];
        bf16 hi = __float2bfloat16(w);
        bf16 lo = __float2bfloat16(w - __bfloat162float(hi));
        g_Wb[m][0][e] = hi;
        g_Wb[m][1][e] = lo;
    }
}

__global__ __launch_bounds__(512, 1)
void proj_attn_kernel(const float* __restrict__ pc, const float* __restrict__ xin)
{
    extern __shared__ char smem[];
    const int tid = threadIdx.x;
    const int w = tid >> 5;
    const int lane = tid & 31;
    const int wm = (w & 3) * 32;
    const int wn = (w >> 2) * 32;
    const int tile = blockIdx.x;
    const int b = blockIdx.y;
    const int n0 = tile * TN;

    float* xs = (float*)(smem + PX);
    float* ws = (float*)(smem + PSTG) + w * 320;

    const bf16* B_HIp = (const bf16*)(smem + PB_HI);
    const bf16* B_LOp = (const bf16*)(smem + PB_LO);
    const bf16* Q_HIp = (const bf16*)(smem + PQ_HI);
    const bf16* Q_LOp = (const bf16*)(smem + PQ_LO);

    // fill pc^T [n][c] split
    for (int idx = tid; idx < 64 * TN; idx += 512) {
        int n = idx & 127, cp = idx >> 7;
        int c = 2 * cp;
        int gn = n0 + n;
        float v0 = 0.f, v1 = 0.f;
        if (gn < NN) {
            v0 = pc[((size_t)b * NC + c) * NN + gn];
            v1 = pc[((size_t)b * NC + c + 1) * NN + gn];
        }
        u32 lop, hip = split_pair(v0, v1, lop);
        *(u32*)(smem + PB_HI + n * LDTB + 2 * c) = hip;
        *(u32*)(smem + PB_LO + n * LDTB + 2 * c) = lop;
    }
    for (int idx = tid; idx < 4 * TN; idx += 512) {
        int ch = idx >> 7, nn = idx & 127;
        int n = n0 + nn;
        xs[ch * 128 + nn] = (n < NN) ? xin[((size_t)b * 4 + ch) * NN + n] : 0.f;
    }
    __syncthreads();

    FragC acc[2][2];
    float vals[8];

    // ---- q GEMM: Wq (gmem) x pc (smem) -> qs (smem, split) ----
    gemm3(g_Wb[0][0], g_Wb[0][1], NC, B_HIp, B_LOp, LDT, wm, wn, acc);
#pragma unroll
    for (int i = 0; i < 2; i++) {
        int o = wm + 16 * i + (lane >> 1);
        float sc = g_par[o], sh = g_par[128 + o];
#pragma unroll
        for (int j = 0; j < 2; j++) {
            frag_vals(ws, acc[i][j], lane, vals);
            int nb = wn + 16 * j + (lane & 1) * 8;
#pragma unroll
            for (int tp = 0; tp < 4; tp++) {
                int n = nb + 2 * tp;
                float v0 = fmaxf(fmaf(vals[2 * tp], sc, sh), 0.f) * INVTEMP;
                float v1 = fmaxf(fmaf(vals[2 * tp + 1], sc, sh), 0.f) * INVTEMP;
                if (n0 + n >= NN) v0 = 0.f;
                if (n0 + n + 1 >= NN) v1 = 0.f;
                u32 lop, hip = split_pair(v0, v1, lop);
                *(u32*)(smem + PQ_HI + o * LDTB + 2 * n) = hip;
                *(u32*)(smem + PQ_LO + o * LDTB + 2 * n) = lop;
            }
        }
    }

    // ---- v GEMM -> gmem split [d][n] ----
    gemm3(g_Wb[2][0], g_Wb[2][1], NC, B_HIp, B_LOp, LDT, wm, wn, acc);
    {
        bf16* vh = g_vh + (size_t)(b * NT + tile) * (TN * NC);
        bf16* vl = g_vl + (size_t)(b * NT + tile) * (TN * NC);
#pragma unroll
        for (int i = 0; i < 2; i++) {
            int d = wm + 16 * i + (lane >> 1);
            float sc = g_par[512 + d], sh = g_par[640 + d];
#pragma unroll
            for (int j = 0; j < 2; j++) {
                frag_vals(ws, acc[i][j], lane, vals);
                int nb = wn + 16 * j + (lane & 1) * 8;
#pragma unroll
                for (int tp = 0; tp < 4; tp++) {
                    float v0 = fmaxf(fmaf(vals[2 * tp], sc, sh), 0.f);
                    float v1 = fmaxf(fmaf(vals[2 * tp + 1], sc, sh), 0.f);
                    u32 lop, hip = split_pair(v0, v1, lop);
                    *(u32*)(vh + d * NC + nb + 2 * tp) = hip;
                    *(u32*)(vl + d * NC + nb + 2 * tp) = lop;
                }
            }
        }
    }

    // ---- k GEMM ----
    gemm3(g_Wb[1][0], g_Wb[1][1], NC, B_HIp, B_LOp, LDT, wm, wn, acc);
    __syncthreads();   // all warps done reading pc tile
#pragma unroll
    for (int i = 0; i < 2; i++) {
        int o = wm + 16 * i + (lane >> 1);
        float sc = g_par[256 + o], sh = g_par[384 + o];
        float w10 = g_par[768 + o], w11 = g_par[896 + o];
        float w20 = g_par[1024 + o], w21 = g_par[1152 + o];
        float bgg = g_par[1280 + o];
#pragma unroll
        for (int j = 0; j < 2; j++) {
            frag_vals(ws, acc[i][j], lane, vals);
            int nb = wn + 16 * j + (lane & 1) * 8;
#pragma unroll
            for (int tp = 0; tp < 4; tp++) {
                int n = nb + 2 * tp;
                float gc0 = fmaf(w10, xs[n],     fmaf(w11, xs[128 + n],     fmaf(w20, xs[256 + n],     fmaf(w21, xs[384 + n],     bgg))));
                float gc1 = fmaf(w10, xs[n + 1], fmaf(w11, xs[128 + n + 1], fmaf(w20, xs[256 + n + 1], fmaf(w21, xs[384 + n + 1], bgg))));
                float v0 = fmaxf(fmaf(vals[2 * tp], sc, sh), 0.f) + gc0;
                float v1 = fmaxf(fmaf(vals[2 * tp + 1], sc, sh), 0.f) + gc1;
                if (n0 + n >= NN) v0 = 0.f;
                if (n0 + n + 1 >= NN) v1 = 0.f;
                u32 lop, hip = split_pair(v0, v1, lop);
                *(u32*)(smem + PB_HI + o * LDTB + 2 * n) = hip;   // kg reuses pc region
                *(u32*)(smem + PB_LO + o * LDTB + 2 * n) = lop;
            }
        }
    }
    __syncthreads();

    // ---- attn partial: qs[c][n] x kg[d][n]^T -> atomicAdd ----
    gemm3(Q_HIp, Q_LOp, LDT, B_HIp, B_LOp, LDT, wm, wn, acc);
#pragma unroll
    for (int i = 0; i < 2; i++) {
        int c = wm + 16 * i + (lane >> 1);
        float* dst = g_attn + ((size_t)b * NC + c) * NC;
#pragma unroll
        for (int j = 0; j < 2; j++) {
            frag_vals(ws, acc[i][j], lane, vals);
            int db = wn + 16 * j + (lane & 1) * 8;
#pragma unroll
            for (int t = 0; t < 8; t++)
                atomicAdd(dst + db + t, vals[t]);
        }
    }
}

__global__ void softmax_kernel()
{
    __shared__ float red[NC];
    const int row = blockIdx.x;
    const int t = threadIdx.x;
    float* a = g_attn + (size_t)row * NC;
    float v = a[t];
    red[t] = v;
    __syncthreads();
    for (int s = 64; s > 0; s >>= 1) {
        if (t < s) red[t] = fmaxf(red[t], red[t + s]);
        __syncthreads();
    }
    float mx = red[0];
    __syncthreads();
    float e = expf(v - mx);
    red[t] = e;
    __syncthreads();
    for (int s = 64; s > 0; s >>= 1) {
        if (t < s) red[t] += red[t + s];
        __syncthreads();
    }
    float p = e / red[0];
    bf16 hi = __float2bfloat16(p);
    bf16 lo = __float2bfloat16(p - __bfloat162float(hi));
    g_ah[(size_t)row * NC + t] = hi;
    g_al[(size_t)row * NC + t] = lo;
}

__global__ __launch_bounds__(256, 2)
void out_kernel(float* __restrict__ out)
{
    __shared__ float ws8[8][320];
    const int tid = threadIdx.x;
    const int w = tid >> 5;
    const int lane = tid & 31;
    const int wm = (w & 3) * 32;
    const int wnb = (w >> 2) * 64;
    const int tile = blockIdx.x;
    const int b = blockIdx.y;
    const int n0 = tile * TN;
    const bool bnd = (n0 + TN > NN);

    const bf16* AH = g_ah + (size_t)b * NC * NC;
    const bf16* AL = g_al + (size_t)b * NC * NC;
    const bf16* BH = g_vh + (size_t)(b * NT + tile) * (TN * NC);
    const bf16* BL = g_vl + (size_t)(b * NT + tile) * (TN * NC);

    FragC acc[2][4];
#pragma unroll
    for (int i = 0; i < 2; i++)
#pragma unroll
        for (int jj = 0; jj < 4; jj++) wmma::fill_fragment(acc[i][jj], 0.f);

#pragma unroll
    for (int k = 0; k < 8; k++) {
        FragA ah[2], al[2];
#pragma unroll
        for (int i = 0; i < 2; i++) {
            wmma::load_matrix_sync(ah[i], AH + (size_t)(wm + 16 * i) * NC + 16 * k, NC);
            wmma::load_matrix_sync(al[i], AL + (size_t)(wm + 16 * i) * NC + 16 * k, NC);
        }
#pragma unroll
        for (int jj = 0; jj < 4; jj++) {
            FragBr bh, bl;
            wmma::load_matrix_sync(bh, BH + (size_t)(16 * k) * NC + wnb + 16 * jj, NC);
            wmma::load_matrix_sync(bl, BL + (size_t)(16 * k) * NC + wnb + 16 * jj, NC);
#pragma unroll
            for (int i = 0; i < 2; i++) {
                wmma::mma_sync(acc[i][jj], ah[i], bh, acc[i][jj]);
                wmma::mma_sync(acc[i][jj], al[i], bh, acc[i][jj]);
                wmma::mma_sync(acc[i][jj], ah[i], bl, acc[i][jj]);
            }
        }
    }

#pragma unroll
    for (int i = 0; i < 2; i++) {
        int c0 = wm + 16 * i;
#pragma unroll
        for (int jj = 0; jj < 4; jj++) {
            int nc0 = n0 + wnb + 16 * jj;
            if (!bnd) {
                wmma::store_matrix_sync(out + ((size_t)b * NC + c0) * NN + nc0,
                                        acc[i][jj], NN, wmma::mem_row_major);
            } else {
                float vals[8];
                frag_vals(ws8[w], acc[i][jj], lane, vals);
                int c = c0 + (lane >> 1);
                int nb = nc0 + (lane & 1) * 8;
                float* dst = out + ((size_t)b * NC + c) * NN;
#pragma unroll
                for (int t = 0; t < 8; t++)
                    if (nb + t < NN) dst[nb + t] = vals[t];
            }
        }
    }
}

extern "C" void kernel_launch(void* const* d_in, const int* in_sizes, int n_in,
                              void* d_out, int out_size)
{
    const float* pc  = (const float*)d_in[0];
    const float* x   = (const float*)d_in[1];
    const float* Wq  = (const float*)d_in[2];
    const float* gq  = (const float*)d_in[3];
    const float* bq  = (const float*)d_in[4];
    const float* mq  = (const float*)d_in[5];
    const float* vq  = (const float*)d_in[6];
    const float* Wk  = (const float*)d_in[7];
    const float* gk  = (const float*)d_in[8];
    const float* bk  = (const float*)d_in[9];
    const float* mk  = (const float*)d_in[10];
    const float* vk  = (const float*)d_in[11];
    const float* Wv  = (const float*)d_in[12];
    const float* gv  = (const float*)d_in[13];
    const float* bv  = (const float*)d_in[14];
    const float* mv  = (const float*)d_in[15];
    const float* vv  = (const float*)d_in[16];
    const float* Wg1 = (const float*)d_in[17];
    const float* bg1 = (const float*)d_in[18];
    const float* Wg2 = (const float*)d_in[19];
    const float* bg2 = (const float*)d_in[20];
    float* out = (float*)d_out;

    cudaFuncSetAttribute(proj_attn_kernel,
                         cudaFuncAttributeMaxDynamicSharedMemorySize, SMEM_A_BYTES);

    prep_kernel<<<1, 512>>>(Wq, Wk, Wv, gq, bq, mq, vq, gk, bk, mk, vk,
                            gv, bv, mv, vv, Wg1, bg1, Wg2, bg2);

    dim3 grid(NT, NB);
    proj_attn_kernel<<<grid, 512, SMEM_A_BYTES>>>(pc, x);
    softmax_kernel<<<NB * NC, NC>>>();
    out_kernel<<<grid, 256>>>(out);
}

// round 12
// speedup vs baseline: 1.1891x; 1.1891x over previous
#include <cuda_runtime.h>
#include <cuda_bf16.h>
#include <mma.h>
#include <math.h>
using namespace nvcuda;

#define NB 8
#define NC 128
#define NN 20000
#define TN 128
#define NT 157
#define LDT 136
#define LDTB 272
#define EPSV 1e-5f
#define INVTEMP 0.08838834764831845f  // 1/sqrt(128)

typedef unsigned int u32;
typedef __nv_bfloat16 bf16;

// scratch (__device__ statics)
__device__ bf16 g_vh[(size_t)NB * NT * TN * NC];   // v hi, [b][tile][d][n]
__device__ bf16 g_vl[(size_t)NB * NT * TN * NC];   // v lo
__device__ float g_attn[(size_t)NB * NC * NC];
__device__ bf16 g_ah[(size_t)NB * NC * NC];        // softmaxed attn hi [b][c][d]
__device__ bf16 g_al[(size_t)NB * NC * NC];
__device__ float g_par[11 * NC];
__device__ bf16 g_Wb[3][2][NC * NC];               // W [o][c] bf16 hi/lo

// proj smem byte offsets
#define PB_HI 0            // pc^T [n][c] (later kg [d][n]) 128x136 bf16
#define PB_LO 34816
#define PW_HI 69632        // W [o][c] staged
#define PW_LO 104448
#define PQ_HI 139264       // qs [c][n]
#define PQ_LO 174080
#define PX    208896       // 512 floats
#define PSTG  210944       // 16 warps x 320 floats
#define SMEM_A_BYTES 231424

typedef wmma::fragment<wmma::matrix_a, 16, 16, 16, bf16, wmma::row_major> FragA;
typedef wmma::fragment<wmma::matrix_b, 16, 16, 16, bf16, wmma::col_major> FragBc;
typedef wmma::fragment<wmma::matrix_b, 16, 16, 16, bf16, wmma::row_major> FragBr;
typedef wmma::fragment<wmma::accumulator, 16, 16, 16, float> FragC;

__device__ __forceinline__ u32 split_pair(float a, float b, u32& lo_pair) {
    bf16 ha = __float2bfloat16(a);
    bf16 hb = __float2bfloat16(b);
    bf16 la = __float2bfloat16(a - __bfloat162float(ha));
    bf16 lb = __float2bfloat16(b - __bfloat162float(hb));
    lo_pair = (u32)__bfloat16_as_ushort(la) | ((u32)__bfloat16_as_ushort(lb) << 16);
    return (u32)__bfloat16_as_ushort(ha) | ((u32)__bfloat16_as_ushort(hb) << 16);
}

// 32x32 warp tile of 128x128x128 GEMM, bf16 split (hh+hl+lh). A row-major, B col-major, smem.
__device__ __forceinline__ void gemm3(const bf16* AH, const bf16* AL,
                                      const bf16* BH, const bf16* BL,
                                      int wm, int wn, FragC acc[2][2])
{
#pragma unroll
    for (int i = 0; i < 2; i++)
#pragma unroll
        for (int j = 0; j < 2; j++) wmma::fill_fragment(acc[i][j], 0.f);
#pragma unroll
    for (int k = 0; k < 8; k++) {
        FragA ah[2], al[2];
        FragBc bh[2], bl[2];
#pragma unroll
        for (int i = 0; i < 2; i++) {
            wmma::load_matrix_sync(ah[i], AH + (wm + 16 * i) * LDT + 16 * k, LDT);
            wmma::load_matrix_sync(al[i], AL + (wm + 16 * i) * LDT + 16 * k, LDT);
        }
#pragma unroll
        for (int j = 0; j < 2; j++) {
            wmma::load_matrix_sync(bh[j], BH + (wn + 16 * j) * LDT + 16 * k, LDT);
            wmma::load_matrix_sync(bl[j], BL + (wn + 16 * j) * LDT + 16 * k, LDT);
        }
#pragma unroll
        for (int i = 0; i < 2; i++)
#pragma unroll
            for (int j = 0; j < 2; j++) {
                wmma::mma_sync(acc[i][j], ah[i], bh[j], acc[i][j]);
                wmma::mma_sync(acc[i][j], ah[i], bl[j], acc[i][j]);
                wmma::mma_sync(acc[i][j], al[i], bh[j], acc[i][j]);
            }
    }
}

__device__ __forceinline__ void frag_vals(float* ws, const FragC& f, int lane, float* v)
{
    wmma::store_matrix_sync(ws, f, 20, wmma::mem_row_major);
    __syncwarp();
    const float* p = ws + (lane >> 1) * 20 + (lane & 1) * 8;
    float4 a = *(const float4*)p;
    float4 b = *(const float4*)(p + 4);
    v[0] = a.x; v[1] = a.y; v[2] = a.z; v[3] = a.w;
    v[4] = b.x; v[5] = b.y; v[6] = b.z; v[7] = b.w;
    __syncwarp();
}

__global__ void prep_kernel(const float* __restrict__ Wq, const float* __restrict__ Wk,
                            const float* __restrict__ Wv,
                            const float* __restrict__ gq, const float* __restrict__ bq,
                            const float* __restrict__ mq, const float* __restrict__ vq,
                            const float* __restrict__ gk, const float* __restrict__ bk,
                            const float* __restrict__ mk, const float* __restrict__ vk,
                            const float* __restrict__ gv, const float* __restrict__ bv,
                            const float* __restrict__ mv, const float* __restrict__ vv,
                            const float* __restrict__ Wg1, const float* __restrict__ bg1,
                            const float* __restrict__ Wg2, const float* __restrict__ bg2)
{
    int t = threadIdx.x;
    if (t < NC) {
        int o = t;
        float s;
        s = gq[o] * rsqrtf(vq[o] + EPSV); g_par[o]       = s; g_par[128 + o] = bq[o] - mq[o] * s;
        s = gk[o] * rsqrtf(vk[o] + EPSV); g_par[256 + o] = s; g_par[384 + o] = bk[o] - mk[o] * s;
        s = gv[o] * rsqrtf(vv[o] + EPSV); g_par[512 + o] = s; g_par[640 + o] = bv[o] - mv[o] * s;
        g_par[768 + o]  = Wg1[o * 2];
        g_par[896 + o]  = Wg1[o * 2 + 1];
        g_par[1024 + o] = Wg2[o * 2];
        g_par[1152 + o] = Wg2[o * 2 + 1];
        g_par[1280 + o] = bg1[o] + bg2[o];
    }
    for (int idx = t; idx < NB * NC * NC; idx += blockDim.x)
        g_attn[idx] = 0.f;
    for (int idx = t; idx < 3 * NC * NC; idx += blockDim.x) {
        int m = idx >> 14, e = idx & 16383;
        const float* Wp = (m == 0) ? Wq : (m == 1) ? Wk : Wv;
        float w = Wp[e];
        bf16 hi = __float2bfloat16(w);
        bf16 lo = __float2bfloat16(w - __bfloat162float(hi));
        g_Wb[m][0][e] = hi;
        g_Wb[m][1][e] = lo;
    }
}

// stage W matrix m (bf16 hi/lo) into smem (ldm 136)
__device__ __forceinline__ void stage_W(char* smem, int m, int tid) {
    const u32* srcH = (const u32*)g_Wb[m][0];
    const u32* srcL = (const u32*)g_Wb[m][1];
#pragma unroll
    for (int k = 0; k < 16; k++) {
        int idx = tid + k * 512;           // 8192 u32 per half
        int row = idx >> 6, cq = idx & 63;
        *(u32*)(smem + PW_HI + row * LDTB + cq * 4) = srcH[idx];
        *(u32*)(smem + PW_LO + row * LDTB + cq * 4) = srcL[idx];
    }
}

__global__ __launch_bounds__(512, 1)
void proj_attn_kernel(const float* __restrict__ pc, const float* __restrict__ xin)
{
    extern __shared__ char smem[];
    const int tid = threadIdx.x;
    const int w = tid >> 5;
    const int lane = tid & 31;
    const int wm = (w & 3) * 32;
    const int wn = (w >> 2) * 32;
    const int tile = blockIdx.x;
    const int b = blockIdx.y;
    const int n0 = tile * TN;

    float* xs = (float*)(smem + PX);
    float* ws = (float*)(smem + PSTG) + w * 320;

    const bf16* B_HIp = (const bf16*)(smem + PB_HI);
    const bf16* B_LOp = (const bf16*)(smem + PB_LO);
    const bf16* W_HIp = (const bf16*)(smem + PW_HI);
    const bf16* W_LOp = (const bf16*)(smem + PW_LO);
    const bf16* Q_HIp = (const bf16*)(smem + PQ_HI);
    const bf16* Q_LOp = (const bf16*)(smem + PQ_LO);

    // fill pc^T [n][c] split
    for (int idx = tid; idx < 64 * TN; idx += 512) {
        int n = idx & 127, cp = idx >> 7;
        int c = 2 * cp;
        int gn = n0 + n;
        float v0 = 0.f, v1 = 0.f;
        if (gn < NN) {
            v0 = pc[((size_t)b * NC + c) * NN + gn];
            v1 = pc[((size_t)b * NC + c + 1) * NN + gn];
        }
        u32 lop, hip = split_pair(v0, v1, lop);
        *(u32*)(smem + PB_HI + n * LDTB + 2 * c) = hip;
        *(u32*)(smem + PB_LO + n * LDTB + 2 * c) = lop;
    }
    for (int idx = tid; idx < 4 * TN; idx += 512) {
        int ch = idx >> 7, nn = idx & 127;
        int n = n0 + nn;
        xs[ch * 128 + nn] = (n < NN) ? xin[((size_t)b * 4 + ch) * NN + n] : 0.f;
    }
    stage_W(smem, 0, tid);   // Wq
    __syncthreads();

    FragC acc[2][2];
    float vals[8];

    // ---- q GEMM -> qs (smem split) ----
    gemm3(W_HIp, W_LOp, B_HIp, B_LOp, wm, wn, acc);
#pragma unroll
    for (int i = 0; i < 2; i++) {
        int o = wm + 16 * i + (lane >> 1);
        float sc = g_par[o], sh = g_par[128 + o];
#pragma unroll
        for (int j = 0; j < 2; j++) {
            frag_vals(ws, acc[i][j], lane, vals);
            int nb = wn + 16 * j + (lane & 1) * 8;
#pragma unroll
            for (int tp = 0; tp < 4; tp++) {
                int n = nb + 2 * tp;
                float v0 = fmaxf(fmaf(vals[2 * tp], sc, sh), 0.f) * INVTEMP;
                float v1 = fmaxf(fmaf(vals[2 * tp + 1], sc, sh), 0.f) * INVTEMP;
                if (n0 + n >= NN) v0 = 0.f;
                if (n0 + n + 1 >= NN) v1 = 0.f;
                u32 lop, hip = split_pair(v0, v1, lop);
                *(u32*)(smem + PQ_HI + o * LDTB + 2 * n) = hip;
                *(u32*)(smem + PQ_LO + o * LDTB + 2 * n) = lop;
            }
        }
    }
    __syncthreads();
    stage_W(smem, 2, tid);   // Wv
    __syncthreads();

    // ---- v GEMM -> gmem split [d][n] ----
    gemm3(W_HIp, W_LOp, B_HIp, B_LOp, wm, wn, acc);
    {
        bf16* vh = g_vh + (size_t)(b * NT + tile) * (TN * NC);
        bf16* vl = g_vl + (size_t)(b * NT + tile) * (TN * NC);
#pragma unroll
        for (int i = 0; i < 2; i++) {
            int d = wm + 16 * i + (lane >> 1);
            float sc = g_par[512 + d], sh = g_par[640 + d];
#pragma unroll
            for (int j = 0; j < 2; j++) {
                frag_vals(ws, acc[i][j], lane, vals);
                int nb = wn + 16 * j + (lane & 1) * 8;
#pragma unroll
                for (int tp = 0; tp < 4; tp++) {
                    float v0 = fmaxf(fmaf(vals[2 * tp], sc, sh), 0.f);
                    float v1 = fmaxf(fmaf(vals[2 * tp + 1], sc, sh), 0.f);
                    u32 lop, hip = split_pair(v0, v1, lop);
                    *(u32*)(vh + d * NC + nb + 2 * tp) = hip;
                    *(u32*)(vl + d * NC + nb + 2 * tp) = lop;
                }
            }
        }
    }
    __syncthreads();
    stage_W(smem, 1, tid);   // Wk
    __syncthreads();

    // ---- k GEMM ----
    gemm3(W_HIp, W_LOp, B_HIp, B_LOp, wm, wn, acc);
    __syncthreads();   // all warps done reading pc tile
#pragma unroll
    for (int i = 0; i < 2; i++) {
        int o = wm + 16 * i + (lane >> 1);
        float sc = g_par[256 + o], sh = g_par[384 + o];
        float w10 = g_par[768 + o], w11 = g_par[896 + o];
        float w20 = g_par[1024 + o], w21 = g_par[1152 + o];
        float bgg = g_par[1280 + o];
#pragma unroll
        for (int j = 0; j < 2; j++) {
            frag_vals(ws, acc[i][j], lane, vals);
            int nb = wn + 16 * j + (lane & 1) * 8;
#pragma unroll
            for (int tp = 0; tp < 4; tp++) {
                int n = nb + 2 * tp;
                float gc0 = fmaf(w10, xs[n],     fmaf(w11, xs[128 + n],     fmaf(w20, xs[256 + n],     fmaf(w21, xs[384 + n],     bgg))));
                float gc1 = fmaf(w10, xs[n + 1], fmaf(w11, xs[128 + n + 1], fmaf(w20, xs[256 + n + 1], fmaf(w21, xs[384 + n + 1], bgg))));
                float v0 = fmaxf(fmaf(vals[2 * tp], sc, sh), 0.f) + gc0;
                float v1 = fmaxf(fmaf(vals[2 * tp + 1], sc, sh), 0.f) + gc1;
                if (n0 + n >= NN) v0 = 0.f;
                if (n0 + n + 1 >= NN) v1 = 0.f;
                u32 lop, hip = split_pair(v0, v1, lop);
                *(u32*)(smem + PB_HI + o * LDTB + 2 * n) = hip;   // kg reuses pc region
                *(u32*)(smem + PB_LO + o * LDTB + 2 * n) = lop;
            }
        }
    }
    __syncthreads();

    // ---- attn partial: qs[c][n] x kg[d][n]^T -> atomicAdd ----
    gemm3(Q_HIp, Q_LOp, B_HIp, B_LOp, wm, wn, acc);
#pragma unroll
    for (int i = 0; i < 2; i++) {
        int c = wm + 16 * i + (lane >> 1);
        float* dst = g_attn + ((size_t)b * NC + c) * NC;
#pragma unroll
        for (int j = 0; j < 2; j++) {
            frag_vals(ws, acc[i][j], lane, vals);
            int db = wn + 16 * j + (lane & 1) * 8;
#pragma unroll
            for (int t = 0; t < 8; t++)
                atomicAdd(dst + db + t, vals[t]);
        }
    }
}

__global__ void softmax_kernel()
{
    __shared__ float red[NC];
    const int row = blockIdx.x;
    const int t = threadIdx.x;
    float* a = g_attn + (size_t)row * NC;
    float v = a[t];
    red[t] = v;
    __syncthreads();
    for (int s = 64; s > 0; s >>= 1) {
        if (t < s) red[t] = fmaxf(red[t], red[t + s]);
        __syncthreads();
    }
    float mx = red[0];
    __syncthreads();
    float e = expf(v - mx);
    red[t] = e;
    __syncthreads();
    for (int s = 64; s > 0; s >>= 1) {
        if (t < s) red[t] += red[t + s];
        __syncthreads();
    }
    float p = e / red[0];
    bf16 hi = __float2bfloat16(p);
    bf16 lo = __float2bfloat16(p - __bfloat162float(hi));
    g_ah[(size_t)row * NC + t] = hi;
    g_al[(size_t)row * NC + t] = lo;
}

__global__ __launch_bounds__(256, 2)
void out_kernel(float* __restrict__ out)
{
    __shared__ float ws8[8][320];
    const int tid = threadIdx.x;
    const int w = tid >> 5;
    const int lane = tid & 31;
    const int wm = (w & 3) * 32;
    const int wnb = (w >> 2) * 64;
    const int tile = blockIdx.x;
    const int b = blockIdx.y;
    const int n0 = tile * TN;
    const bool bnd = (n0 + TN > NN);

    const bf16* AH = g_ah + (size_t)b * NC * NC;
    const bf16* AL = g_al + (size_t)b * NC * NC;
    const bf16* BH = g_vh + (size_t)(b * NT + tile) * (TN * NC);
    const bf16* BL = g_vl + (size_t)(b * NT + tile) * (TN * NC);

    FragC acc[2][4];
#pragma unroll
    for (int i = 0; i < 2; i++)
#pragma unroll
        for (int jj = 0; jj < 4; jj++) wmma::fill_fragment(acc[i][jj], 0.f);

#pragma unroll
    for (int k = 0; k < 8; k++) {
        FragA ah[2], al[2];
#pragma unroll
        for (int i = 0; i < 2; i++) {
            wmma::load_matrix_sync(ah[i], AH + (size_t)(wm + 16 * i) * NC + 16 * k, NC);
            wmma::load_matrix_sync(al[i], AL + (size_t)(wm + 16 * i) * NC + 16 * k, NC);
        }
#pragma unroll
        for (int jj = 0; jj < 4; jj++) {
            FragBr bh, bl;
            wmma::load_matrix_sync(bh, BH + (size_t)(16 * k) * NC + wnb + 16 * jj, NC);
            wmma::load_matrix_sync(bl, BL + (size_t)(16 * k) * NC + wnb + 16 * jj, NC);
#pragma unroll
            for (int i = 0; i < 2; i++) {
                wmma::mma_sync(acc[i][jj], ah[i], bh, acc[i][jj]);
                wmma::mma_sync(acc[i][jj], al[i], bh, acc[i][jj]);
                wmma::mma_sync(acc[i][jj], ah[i], bl, acc[i][jj]);
            }
        }
    }

#pragma unroll
    for (int i = 0; i < 2; i++) {
        int c0 = wm + 16 * i;
#pragma unroll
        for (int jj = 0; jj < 4; jj++) {
            int nc0 = n0 + wnb + 16 * jj;
            if (!bnd) {
                wmma::store_matrix_sync(out + ((size_t)b * NC + c0) * NN + nc0,
                                        acc[i][jj], NN, wmma::mem_row_major);
            } else {
                float vals[8];
                frag_vals(ws8[w], acc[i][jj], lane, vals);
                int c = c0 + (lane >> 1);
                int nb = nc0 + (lane & 1) * 8;
                float* dst = out + ((size_t)b * NC + c) * NN;
#pragma unroll
                for (int t = 0; t < 8; t++)
                    if (nb + t < NN) dst[nb + t] = vals[t];
            }
        }
    }
}

extern "C" void kernel_launch(void* const* d_in, const int* in_sizes, int n_in,
                              void* d_out, int out_size)
{
    const float* pc  = (const float*)d_in[0];
    const float* x   = (const float*)d_in[1];
    const float* Wq  = (const float*)d_in[2];
    const float* gq  = (const float*)d_in[3];
    const float* bq  = (const float*)d_in[4];
    const float* mq  = (const float*)d_in[5];
    const float* vq  = (const float*)d_in[6];
    const float* Wk  = (const float*)d_in[7];
    const float* gk  = (const float*)d_in[8];
    const float* bk  = (const float*)d_in[9];
    const float* mk  = (const float*)d_in[10];
    const float* vk  = (const float*)d_in[11];
    const float* Wv  = (const float*)d_in[12];
    const float* gv  = (const float*)d_in[13];
    const float* bv  = (const float*)d_in[14];
    const float* mv  = (const float*)d_in[15];
    const float* vv  = (const float*)d_in[16];
    const float* Wg1 = (const float*)d_in[17];
    const float* bg1 = (const float*)d_in[18];
    const float* Wg2 = (const float*)d_in[19];
    const float* bg2 = (const float*)d_in[20];
    float* out = (float*)d_out;

    cudaFuncSetAttribute(proj_attn_kernel,
                         cudaFuncAttributeMaxDynamicSharedMemorySize, SMEM_A_BYTES);

    prep_kernel<<<1, 512>>>(Wq, Wk, Wv, gq, bq, mq, vq, gk, bk, mk, vk,
                            gv, bv, mv, vv, Wg1, bg1, Wg2, bg2);

    dim3 grid(NT, NB);
    proj_attn_kernel<<<grid, 512, SMEM_A_BYTES>>>(pc, x);
    softmax_kernel<<<NB * NC, NC>>>();
    out_kernel<<<grid, 256>>>(out);
}

// round 17
// speedup vs baseline: 1.3716x; 1.1535x over previous
#include <cuda_runtime.h>
#include <cuda_bf16.h>
#include <mma.h>
#include <math.h>
using namespace nvcuda;

#define NB 8
#define NC 128
#define NN 20000
#define TN 128
#define NT 157
#define LDT 136
#define LDTB 272
#define EPSV 1e-5f
#define INVTEMP 0.08838834764831845f  // 1/sqrt(128)

typedef unsigned int u32;
typedef __nv_bfloat16 bf16;

// scratch (__device__ statics)
__device__ bf16 g_vh[(size_t)NB * NT * TN * NC];   // v hi, [b][tile][d][n]
__device__ bf16 g_vl[(size_t)NB * NT * TN * NC];   // v lo
__device__ float g_attn[(size_t)NB * NC * NC];
__device__ bf16 g_ah[(size_t)NB * NC * NC];        // softmaxed attn hi [b][c][d]
__device__ bf16 g_al[(size_t)NB * NC * NC];
__device__ float g_par[11 * NC];
__device__ bf16 g_Wb[3][2][NC * NC];               // W [o][c] bf16 hi/lo

// proj smem byte offsets
#define PB_HI 0            // pc^T [n][c] (later kg [d][n]) 128x136 bf16
#define PB_LO 34816
#define PW_HI 69632        // W [o][c] staged
#define PW_LO 104448
#define PQ_HI 139264       // qs [c][n]
#define PQ_LO 174080
#define PX    208896       // 512 floats
#define PSTG  210944       // 16 warps x 320 floats
#define SMEM_A_BYTES 231424

// out kernel dynamic smem: staged B tile (v) hi/lo, [n][LDT]
#define OB_HI 0
#define OB_LO 34816
#define SMEM_O_BYTES 69632

typedef wmma::fragment<wmma::matrix_a, 16, 16, 16, bf16, wmma::row_major> FragA;
typedef wmma::fragment<wmma::matrix_b, 16, 16, 16, bf16, wmma::col_major> FragBc;
typedef wmma::fragment<wmma::matrix_b, 16, 16, 16, bf16, wmma::row_major> FragBr;
typedef wmma::fragment<wmma::accumulator, 16, 16, 16, float> FragC;

__device__ __forceinline__ u32 split_pair(float a, float b, u32& lo_pair) {
    bf16 ha = __float2bfloat16(a);
    bf16 hb = __float2bfloat16(b);
    bf16 la = __float2bfloat16(a - __bfloat162float(ha));
    bf16 lb = __float2bfloat16(b - __bfloat162float(hb));
    lo_pair = (u32)__bfloat16_as_ushort(la) | ((u32)__bfloat16_as_ushort(lb) << 16);
    return (u32)__bfloat16_as_ushort(ha) | ((u32)__bfloat16_as_ushort(hb) << 16);
}

// 32x32 warp tile of 128x128x128 GEMM, bf16 split (hh+hl+lh). A row-major, B col-major, smem.
__device__ __forceinline__ void gemm3(const bf16* AH, const bf16* AL,
                                      const bf16* BH, const bf16* BL,
                                      int wm, int wn, FragC acc[2][2])
{
#pragma unroll
    for (int i = 0; i < 2; i++)
#pragma unroll
        for (int j = 0; j < 2; j++) wmma::fill_fragment(acc[i][j], 0.f);
#pragma unroll
    for (int k = 0; k < 8; k++) {
        FragA ah[2], al[2];
        FragBc bh[2], bl[2];
#pragma unroll
        for (int i = 0; i < 2; i++) {
            wmma::load_matrix_sync(ah[i], AH + (wm + 16 * i) * LDT + 16 * k, LDT);
            wmma::load_matrix_sync(al[i], AL + (wm + 16 * i) * LDT + 16 * k, LDT);
        }
#pragma unroll
        for (int j = 0; j < 2; j++) {
            wmma::load_matrix_sync(bh[j], BH + (wn + 16 * j) * LDT + 16 * k, LDT);
            wmma::load_matrix_sync(bl[j], BL + (wn + 16 * j) * LDT + 16 * k, LDT);
        }
#pragma unroll
        for (int i = 0; i < 2; i++)
#pragma unroll
            for (int j = 0; j < 2; j++) {
                wmma::mma_sync(acc[i][j], ah[i], bh[j], acc[i][j]);
                wmma::mma_sync(acc[i][j], ah[i], bl[j], acc[i][j]);
                wmma::mma_sync(acc[i][j], al[i], bh[j], acc[i][j]);
            }
    }
}

__device__ __forceinline__ void frag_vals(float* ws, const FragC& f, int lane, float* v)
{
    wmma::store_matrix_sync(ws, f, 20, wmma::mem_row_major);
    __syncwarp();
    const float* p = ws + (lane >> 1) * 20 + (lane & 1) * 8;
    float4 a = *(const float4*)p;
    float4 b = *(const float4*)(p + 4);
    v[0] = a.x; v[1] = a.y; v[2] = a.z; v[3] = a.w;
    v[4] = b.x; v[5] = b.y; v[6] = b.z; v[7] = b.w;
    __syncwarp();
}

__global__ void prep_kernel(const float* __restrict__ Wq, const float* __restrict__ Wk,
                            const float* __restrict__ Wv,
                            const float* __restrict__ gq, const float* __restrict__ bq,
                            const float* __restrict__ mq, const float* __restrict__ vq,
                            const float* __restrict__ gk, const float* __restrict__ bk,
                            const float* __restrict__ mk, const float* __restrict__ vk,
                            const float* __restrict__ gv, const float* __restrict__ bv,
                            const float* __restrict__ mv, const float* __restrict__ vv,
                            const float* __restrict__ Wg1, const float* __restrict__ bg1,
                            const float* __restrict__ Wg2, const float* __restrict__ bg2)
{
    int gt = blockIdx.x * blockDim.x + threadIdx.x;
    int nth = gridDim.x * blockDim.x;
    if (blockIdx.x == 0 && threadIdx.x < NC) {
        int o = threadIdx.x;
        float s;
        s = gq[o] * rsqrtf(vq[o] + EPSV); g_par[o]       = s; g_par[128 + o] = bq[o] - mq[o] * s;
        s = gk[o] * rsqrtf(vk[o] + EPSV); g_par[256 + o] = s; g_par[384 + o] = bk[o] - mk[o] * s;
        s = gv[o] * rsqrtf(vv[o] + EPSV); g_par[512 + o] = s; g_par[640 + o] = bv[o] - mv[o] * s;
        g_par[768 + o]  = Wg1[o * 2];
        g_par[896 + o]  = Wg1[o * 2 + 1];
        g_par[1024 + o] = Wg2[o * 2];
        g_par[1152 + o] = Wg2[o * 2 + 1];
        g_par[1280 + o] = bg1[o] + bg2[o];
    }
    for (int idx = gt; idx < NB * NC * NC; idx += nth)
        g_attn[idx] = 0.f;
    for (int idx = gt; idx < 3 * NC * NC; idx += nth) {
        int m = idx >> 14, e = idx & 16383;
        const float* Wp = (m == 0) ? Wq : (m == 1) ? Wk : Wv;
        float w = Wp[e];
        bf16 hi = __float2bfloat16(w);
        bf16 lo = __float2bfloat16(w - __bfloat162float(hi));
        g_Wb[m][0][e] = hi;
        g_Wb[m][1][e] = lo;
    }
}

// stage W matrix m (bf16 hi/lo) into smem (ldm 136)
__device__ __forceinline__ void stage_W(char* smem, int m, int tid) {
    const u32* srcH = (const u32*)g_Wb[m][0];
    const u32* srcL = (const u32*)g_Wb[m][1];
#pragma unroll
    for (int k = 0; k < 16; k++) {
        int idx = tid + k * 512;           // 8192 u32 per half
        int row = idx >> 6, cq = idx & 63;
        *(u32*)(smem + PW_HI + row * LDTB + cq * 4) = srcH[idx];
        *(u32*)(smem + PW_LO + row * LDTB + cq * 4) = srcL[idx];
    }
}

__global__ __launch_bounds__(512, 1)
void proj_attn_kernel(const float* __restrict__ pc, const float* __restrict__ xin)
{
    extern __shared__ char smem[];
    const int tid = threadIdx.x;
    const int w = tid >> 5;
    const int lane = tid & 31;
    const int wm = (w & 3) * 32;
    const int wn = (w >> 2) * 32;
    const int tile = blockIdx.x;
    const int b = blockIdx.y;
    const int n0 = tile * TN;

    float* xs = (float*)(smem + PX);
    float* ws = (float*)(smem + PSTG) + w * 320;

    const bf16* B_HIp = (const bf16*)(smem + PB_HI);
    const bf16* B_LOp = (const bf16*)(smem + PB_LO);
    const bf16* W_HIp = (const bf16*)(smem + PW_HI);
    const bf16* W_LOp = (const bf16*)(smem + PW_LO);
    const bf16* Q_HIp = (const bf16*)(smem + PQ_HI);
    const bf16* Q_LOp = (const bf16*)(smem + PQ_LO);

    // fill pc^T [n][c] split
    for (int idx = tid; idx < 64 * TN; idx += 512) {
        int n = idx & 127, cp = idx >> 7;
        int c = 2 * cp;
        int gn = n0 + n;
        float v0 = 0.f, v1 = 0.f;
        if (gn < NN) {
            v0 = pc[((size_t)b * NC + c) * NN + gn];
            v1 = pc[((size_t)b * NC + c + 1) * NN + gn];
        }
        u32 lop, hip = split_pair(v0, v1, lop);
        *(u32*)(smem + PB_HI + n * LDTB + 2 * c) = hip;
        *(u32*)(smem + PB_LO + n * LDTB + 2 * c) = lop;
    }
    for (int idx = tid; idx < 4 * TN; idx += 512) {
        int ch = idx >> 7, nn = idx & 127;
        int n = n0 + nn;
        xs[ch * 128 + nn] = (n < NN) ? xin[((size_t)b * 4 + ch) * NN + n] : 0.f;
    }
    stage_W(smem, 0, tid);   // Wq
    __syncthreads();

    FragC acc[2][2];
    float vals[8];

    // ---- q GEMM ----
    gemm3(W_HIp, W_LOp, B_HIp, B_LOp, wm, wn, acc);
    __syncthreads();          // all warps done reading PW
    stage_W(smem, 2, tid);    // Wv (overlaps with q epilogue below)
#pragma unroll
    for (int i = 0; i < 2; i++) {
        int o = wm + 16 * i + (lane >> 1);
        float sc = g_par[o], sh = g_par[128 + o];
#pragma unroll
        for (int j = 0; j < 2; j++) {
            frag_vals(ws, acc[i][j], lane, vals);
            int nb = wn + 16 * j + (lane & 1) * 8;
#pragma unroll
            for (int tp = 0; tp < 4; tp++) {
                int n = nb + 2 * tp;
                float v0 = fmaxf(fmaf(vals[2 * tp], sc, sh), 0.f) * INVTEMP;
                float v1 = fmaxf(fmaf(vals[2 * tp + 1], sc, sh), 0.f) * INVTEMP;
                if (n0 + n >= NN) v0 = 0.f;
                if (n0 + n + 1 >= NN) v1 = 0.f;
                u32 lop, hip = split_pair(v0, v1, lop);
                *(u32*)(smem + PQ_HI + o * LDTB + 2 * n) = hip;
                *(u32*)(smem + PQ_LO + o * LDTB + 2 * n) = lop;
            }
        }
    }
    __syncthreads();

    // ---- v GEMM ----
    gemm3(W_HIp, W_LOp, B_HIp, B_LOp, wm, wn, acc);
    __syncthreads();          // PW free
    stage_W(smem, 1, tid);    // Wk (overlaps with v epilogue)
    {
        bf16* vh = g_vh + (size_t)(b * NT + tile) * (TN * NC);
        bf16* vl = g_vl + (size_t)(b * NT + tile) * (TN * NC);
#pragma unroll
        for (int i = 0; i < 2; i++) {
            int d = wm + 16 * i + (lane >> 1);
            float sc = g_par[512 + d], sh = g_par[640 + d];
#pragma unroll
            for (int j = 0; j < 2; j++) {
                frag_vals(ws, acc[i][j], lane, vals);
                int nb = wn + 16 * j + (lane & 1) * 8;
#pragma unroll
                for (int tp = 0; tp < 4; tp++) {
                    float v0 = fmaxf(fmaf(vals[2 * tp], sc, sh), 0.f);
                    float v1 = fmaxf(fmaf(vals[2 * tp + 1], sc, sh), 0.f);
                    u32 lop, hip = split_pair(v0, v1, lop);
                    *(u32*)(vh + d * NC + nb + 2 * tp) = hip;
                    *(u32*)(vl + d * NC + nb + 2 * tp) = lop;
                }
            }
        }
    }
    __syncthreads();

    // ---- k GEMM ----
    gemm3(W_HIp, W_LOp, B_HIp, B_LOp, wm, wn, acc);
    __syncthreads();   // all warps done reading PB (pc tile)
#pragma unroll
    for (int i = 0; i < 2; i++) {
        int o = wm + 16 * i + (lane >> 1);
        float sc = g_par[256 + o], sh = g_par[384 + o];
        float w10 = g_par[768 + o], w11 = g_par[896 + o];
        float w20 = g_par[1024 + o], w21 = g_par[1152 + o];
        float bgg = g_par[1280 + o];
#pragma unroll
        for (int j = 0; j < 2; j++) {
            frag_vals(ws, acc[i][j], lane, vals);
            int nb = wn + 16 * j + (lane & 1) * 8;
#pragma unroll
            for (int tp = 0; tp < 4; tp++) {
                int n = nb + 2 * tp;
                float gc0 = fmaf(w10, xs[n],     fmaf(w11, xs[128 + n],     fmaf(w20, xs[256 + n],     fmaf(w21, xs[384 + n],     bgg))));
                float gc1 = fmaf(w10, xs[n + 1], fmaf(w11, xs[128 + n + 1], fmaf(w20, xs[256 + n + 1], fmaf(w21, xs[384 + n + 1], bgg))));
                float v0 = fmaxf(fmaf(vals[2 * tp], sc, sh), 0.f) + gc0;
                float v1 = fmaxf(fmaf(vals[2 * tp + 1], sc, sh), 0.f) + gc1;
                if (n0 + n >= NN) v0 = 0.f;
                if (n0 + n + 1 >= NN) v1 = 0.f;
                u32 lop, hip = split_pair(v0, v1, lop);
                *(u32*)(smem + PB_HI + o * LDTB + 2 * n) = hip;   // kg reuses pc region
                *(u32*)(smem + PB_LO + o * LDTB + 2 * n) = lop;
            }
        }
    }
    __syncthreads();

    // ---- attn partial: qs[c][n] x kg[d][n]^T -> atomicAdd ----
    gemm3(Q_HIp, Q_LOp, B_HIp, B_LOp, wm, wn, acc);
#pragma unroll
    for (int i = 0; i < 2; i++) {
        int c = wm + 16 * i + (lane >> 1);
        float* dst = g_attn + ((size_t)b * NC + c) * NC;
#pragma unroll
        for (int j = 0; j < 2; j++) {
            frag_vals(ws, acc[i][j], lane, vals);
            int db = wn + 16 * j + (lane & 1) * 8;
#pragma unroll
            for (int t = 0; t < 8; t++)
                atomicAdd(dst + db + t, vals[t]);
        }
    }
}

__global__ void softmax_kernel()
{
    __shared__ float red[NC];
    const int row = blockIdx.x;
    const int t = threadIdx.x;
    float* a = g_attn + (size_t)row * NC;
    float v = a[t];
    red[t] = v;
    __syncthreads();
    for (int s = 64; s > 0; s >>= 1) {
        if (t < s) red[t] = fmaxf(red[t], red[t + s]);
        __syncthreads();
    }
    float mx = red[0];
    __syncthreads();
    float e = expf(v - mx);
    red[t] = e;
    __syncthreads();
    for (int s = 64; s > 0; s >>= 1) {
        if (t < s) red[t] += red[t + s];
        __syncthreads();
    }
    float p = e / red[0];
    bf16 hi = __float2bfloat16(p);
    bf16 lo = __float2bfloat16(p - __bfloat162float(hi));
    g_ah[(size_t)row * NC + t] = hi;
    g_al[(size_t)row * NC + t] = lo;
}

__global__ __launch_bounds__(256, 2)
void out_kernel(float* __restrict__ out)
{
    extern __shared__ char osm[];
    __shared__ float ws8[8][320];
    const int tid = threadIdx.x;
    const int w = tid >> 5;
    const int lane = tid & 31;
    const int wm = (w & 3) * 32;
    const int wnb = (w >> 2) * 64;
    const int tile = blockIdx.x;
    const int b = blockIdx.y;
    const int n0 = tile * TN;
    const bool bnd = (n0 + TN > NN);

    const bf16* AH = g_ah + (size_t)b * NC * NC;
    const bf16* AL = g_al + (size_t)b * NC * NC;
    const u32* BHs = (const u32*)(g_vh + (size_t)(b * NT + tile) * (TN * NC));
    const u32* BLs = (const u32*)(g_vl + (size_t)(b * NT + tile) * (TN * NC));

    // stage B (v tile) into smem [n][LDT] — pure u32 copy, coalesced
    {
        u32* dh = (u32*)(osm + OB_HI);
        u32* dl = (u32*)(osm + OB_LO);
#pragma unroll
        for (int k = 0; k < 32; k++) {
            int idx = tid + k * 256;       // 8192 u32 per half
            int n = idx >> 6, q = idx & 63;
            dh[n * (LDT / 2) + q] = BHs[idx];
            dl[n * (LDT / 2) + q] = BLs[idx];
        }
    }
    __syncthreads();

    const bf16* BH = (const bf16*)(osm + OB_HI);
    const bf16* BL = (const bf16*)(osm + OB_LO);

    FragC acc[2][4];
#pragma unroll
    for (int i = 0; i < 2; i++)
#pragma unroll
        for (int jj = 0; jj < 4; jj++) wmma::fill_fragment(acc[i][jj], 0.f);

#pragma unroll
    for (int k = 0; k < 8; k++) {
        FragA ah[2], al[2];
#pragma unroll
        for (int i = 0; i < 2; i++) {
            wmma::load_matrix_sync(ah[i], AH + (size_t)(wm + 16 * i) * NC + 16 * k, NC);
            wmma::load_matrix_sync(al[i], AL + (size_t)(wm + 16 * i) * NC + 16 * k, NC);
        }
#pragma unroll
        for (int jj = 0; jj < 4; jj++) {
            FragBr bh, bl;
            wmma::load_matrix_sync(bh, BH + (16 * k) * LDT + wnb + 16 * jj, LDT);
            wmma::load_matrix_sync(bl, BL + (16 * k) * LDT + wnb + 16 * jj, LDT);
#pragma unroll
            for (int i = 0; i < 2; i++) {
                wmma::mma_sync(acc[i][jj], ah[i], bh, acc[i][jj]);
                wmma::mma_sync(acc[i][jj], al[i], bh, acc[i][jj]);
                wmma::mma_sync(acc[i][jj], ah[i], bl, acc[i][jj]);
            }
        }
    }

#pragma unroll
    for (int i = 0; i < 2; i++) {
        int c0 = wm + 16 * i;
#pragma unroll
        for (int jj = 0; jj < 4; jj++) {
            int nc0 = n0 + wnb + 16 * jj;
            if (!bnd) {
                wmma::store_matrix_sync(out + ((size_t)b * NC + c0) * NN + nc0,
                                        acc[i][jj], NN, wmma::mem_row_major);
            } else {
                float vals[8];
                frag_vals(ws8[w], acc[i][jj], lane, vals);
                int c = c0 + (lane >> 1);
                int nb = nc0 + (lane & 1) * 8;
                float* dst = out + ((size_t)b * NC + c) * NN;
#pragma unroll
                for (int t = 0; t < 8; t++)
                    if (nb + t < NN) dst[nb + t] = vals[t];
            }
        }
    }
}

extern "C" void kernel_launch(void* const* d_in, const int* in_sizes, int n_in,
                              void* d_out, int out_size)
{
    const float* pc  = (const float*)d_in[0];
    const float* x   = (const float*)d_in[1];
    const float* Wq  = (const float*)d_in[2];
    const float* gq  = (const float*)d_in[3];
    const float* bq  = (const float*)d_in[4];
    const float* mq  = (const float*)d_in[5];
    const float* vq  = (const float*)d_in[6];
    const float* Wk  = (const float*)d_in[7];
    const float* gk  = (const float*)d_in[8];
    const float* bk  = (const float*)d_in[9];
    const float* mk  = (const float*)d_in[10];
    const float* vk  = (const float*)d_in[11];
    const float* Wv  = (const float*)d_in[12];
    const float* gv  = (const float*)d_in[13];
    const float* bv  = (const float*)d_in[14];
    const float* mv  = (const float*)d_in[15];
    const float* vv  = (const float*)d_in[16];
    const float* Wg1 = (const float*)d_in[17];
    const float* bg1 = (const float*)d_in[18];
    const float* Wg2 = (const float*)d_in[19];
    const float* bg2 = (const float*)d_in[20];
    float* out = (float*)d_out;

    cudaFuncSetAttribute(proj_attn_kernel,
                         cudaFuncAttributeMaxDynamicSharedMemorySize, SMEM_A_BYTES);
    cudaFuncSetAttribute(out_kernel,
                         cudaFuncAttributeMaxDynamicSharedMemorySize, SMEM_O_BYTES);

    prep_kernel<<<32, 512>>>(Wq, Wk, Wv, gq, bq, mq, vq, gk, bk, mk, vk,
                             gv, bv, mv, vv, Wg1, bg1, Wg2, bg2);

    dim3 grid(NT, NB);
    proj_attn_kernel<<<grid, 512, SMEM_A_BYTES>>>(pc, x);
    softmax_kernel<<<NB * NC, NC>>>();
    out_kernel<<<grid, 256, SMEM_O_BYTES>>>(out);
}